// round 14
// baseline (speedup 1.0000x reference)
#include <cuda_runtime.h>
#include <cuda_fp16.h>
#include <cstdint>

#define N_EDGES  2000000
#define NUM_SEGS 500000
#define HID      128
#define NRB      4
#define TILE_M   384
#define NTILES   ((N_EDGES + TILE_M - 1) / TILE_M)   /* 5209, last tile 128 rows */
#define NTHREADS 384
#define WSTRIDE  136                  /* halves per W row: 128 + 8 pad */
#define WINSTR   24                   /* halves per W_in row: 16 + 8 pad */
#define OWSTR    136                  /* halves per w_out ldsm row */
#define RMS_EPS  1.1920928955078125e-07f

/* SMEM layout (bytes) */
#define OFF_W     0
#define SZ_W      (NRB * HID * WSTRIDE * 2)          /* 139264 */
#define OFF_WIN16 (OFF_W + SZ_W)                     /* half[128*24] ldsm layout */
#define OFF_BRESH (OFF_WIN16 + HID * WINSTR * 2)     /* half2[4*64]  */
#define OFF_WOH   (OFF_BRESH + NRB * 64 * 4)         /* half[8*136] w_out ldsm B-layout */
#define SMEM_BYTES (OFF_WOH + 8 * OWSTR * 2)

__device__ float    g_logits[N_EDGES];
__device__ unsigned g_segmax[NUM_SEGS];
__device__ float    g_segsum[NUM_SEGS];
__device__ unsigned g_count = 0;
__device__ unsigned g_gen   = 0;

__device__ __forceinline__ void grid_bar() {
    __syncthreads();
    if (threadIdx.x == 0) {
        __threadfence();
        unsigned gen = *((volatile unsigned*)&g_gen);
        if (atomicAdd(&g_count, 1u) == gridDim.x - 1) {
            g_count = 0;
            __threadfence();
            atomicAdd(&g_gen, 1u);
        } else {
            while (*((volatile unsigned*)&g_gen) == gen) { }
            __threadfence();
        }
    }
    __syncthreads();
}

__device__ __forceinline__ unsigned enc_f(float f) {
    unsigned b = __float_as_uint(f);
    return (b & 0x80000000u) ? ~b : (b | 0x80000000u);
}
__device__ __forceinline__ float dec_f(unsigned k) {
    unsigned b = (k & 0x80000000u) ? (k & 0x7FFFFFFFu) : ~k;
    return __uint_as_float(b);
}
__device__ __forceinline__ uint32_t pack_h2(float lo, float hi) {
    __half2 h = __floats2half2_rn(lo, hi);
    return *reinterpret_cast<uint32_t*>(&h);
}
__device__ __forceinline__ float2 unpack_h2(uint32_t u) {
    return __half22float2(*reinterpret_cast<__half2*>(&u));
}
__device__ __forceinline__ uint32_t hadd2_u(uint32_t a, uint32_t b) {
    __half2 r = __hadd2(*reinterpret_cast<__half2*>(&a), *reinterpret_cast<__half2*>(&b));
    return *reinterpret_cast<uint32_t*>(&r);
}
__device__ __forceinline__ uint32_t hmax2z_u(uint32_t a) {
    __half2 z = __float2half2_rn(0.f);
    __half2 r = __hmax2(*reinterpret_cast<__half2*>(&a), z);
    return *reinterpret_cast<uint32_t*>(&r);
}
__device__ __forceinline__ uint32_t hfma2_u(uint32_t a, uint32_t b, uint32_t c) {
    __half2 r = __hfma2(*reinterpret_cast<__half2*>(&a),
                        *reinterpret_cast<__half2*>(&b),
                        *reinterpret_cast<__half2*>(&c));
    return *reinterpret_cast<uint32_t*>(&r);
}
__device__ __forceinline__ void ldsm_x4(uint32_t& r0, uint32_t& r1, uint32_t& r2, uint32_t& r3,
                                        uint32_t addr) {
    asm volatile("ldmatrix.sync.aligned.m8n8.x4.shared.b16 {%0,%1,%2,%3}, [%4];\n"
                 : "=r"(r0), "=r"(r1), "=r"(r2), "=r"(r3) : "r"(addr));
}
__device__ __forceinline__ void ldsm_x2(uint32_t& r0, uint32_t& r1, uint32_t addr) {
    asm volatile("ldmatrix.sync.aligned.m8n8.x2.shared.b16 {%0,%1}, [%2];\n"
                 : "=r"(r0), "=r"(r1) : "r"(addr));
}
__device__ __forceinline__ void mma16816h(uint32_t* d,
        uint32_t a0, uint32_t a1, uint32_t a2, uint32_t a3,
        uint32_t b0, uint32_t b1) {
    asm volatile("mma.sync.aligned.m16n8k16.row.col.f16.f16.f16.f16 "
                 "{%0,%1}, {%2,%3,%4,%5}, {%6,%7}, {%0,%1};\n"
                 : "+r"(d[0]), "+r"(d[1])
                 : "r"(a0), "r"(a1), "r"(a2), "r"(a3), "r"(b0), "r"(b1));
}
__device__ __forceinline__ void mma16816f(float* d,
        uint32_t a0, uint32_t a1, uint32_t a2, uint32_t a3,
        uint32_t b0, uint32_t b1) {
    asm volatile("mma.sync.aligned.m16n8k16.row.col.f32.f16.f16.f32 "
                 "{%0,%1,%2,%3}, {%4,%5,%6,%7}, {%8,%9}, {%0,%1,%2,%3};\n"
                 : "+f"(d[0]), "+f"(d[1]), "+f"(d[2]), "+f"(d[3])
                 : "r"(a0), "r"(a1), "r"(a2), "r"(a3), "r"(b0), "r"(b1));
}

__global__ void __launch_bounds__(NTHREADS, 1)
mlp_kernel(const float* __restrict__ ef, const int* __restrict__ ids,
           const float* __restrict__ W_in, const float* __restrict__ b_in,
           const float* __restrict__ rms_w, const float* __restrict__ W_res,
           const float* __restrict__ b_res, const float* __restrict__ W_out,
           const float* __restrict__ b_out, float* __restrict__ out)
{
    extern __shared__ char smem[];
    __half*   Wh   = (__half*)(smem + OFF_W);
    __half*   winh = (__half*)(smem + OFF_WIN16);
    uint32_t* brsh = (uint32_t*)(smem + OFF_BRESH);
    __half*   woh  = (__half*)(smem + OFF_WOH);

    const int tid = threadIdx.x;
    const int gtid = blockIdx.x * NTHREADS + tid;
    const int gstride = gridDim.x * NTHREADS;

    /* ---- phase 0: init segment accumulators (replaces init_kernel) ---- */
    for (int i = gtid; i < NUM_SEGS; i += gstride) {
        g_segmax[i] = 0u;
        g_segsum[i] = 0.f;
    }

    /* ---- stage weights once per CTA; fold rms_w (per-k) into W_res ---- */
    for (int idx = tid; idx < NRB * HID * HID; idx += NTHREADS) {
        int i   = idx >> 14;
        int rem = idx & 16383;
        int n   = rem >> 7;
        int k   = rem & 127;
        float w = W_res[idx] * rms_w[i * HID + k];
        Wh[(i * HID + n) * WSTRIDE + k] = __float2half(w);
    }
    for (int idx = tid; idx < HID * 16; idx += NTHREADS) {
        int n = idx >> 4, k = idx & 15;
        float v = (k < 3) ? W_in[n * 3 + k] : (k == 3 ? b_in[n] : 0.f);
        winh[n * WINSTR + k] = __float2half(v);
    }
    for (int idx = tid; idx < HID * (WINSTR - 16); idx += NTHREADS) {
        int n = idx / (WINSTR - 16), k = 16 + idx % (WINSTR - 16);
        winh[n * WINSTR + k] = __float2half(0.f);
    }
    for (int idx = tid; idx < 8 * OWSTR; idx += NTHREADS) {
        int n = idx / OWSTR, k = idx % OWSTR;
        woh[idx] = __float2half((n == 0 && k < HID) ? W_out[k] : 0.f);
    }
    for (int idx = tid; idx < NRB * 64; idx += NTHREADS) {
        int i = idx >> 6, c2 = idx & 63;
        brsh[idx] = pack_h2(b_res[i * HID + 2 * c2], b_res[i * HID + 2 * c2 + 1]);
    }

    grid_bar();   /* segmax/segsum init visible before any atomicMax */

    const float bout = b_out[0];
    const int warp = tid >> 5, lane = tid & 31;
    const int q = lane & 3, gid = lane >> 2;

    uint32_t wbase = (uint32_t)__cvta_generic_to_shared(Wh);
    uint32_t laneB = wbase +
        ((((lane & 7) + ((lane >> 4) & 1) * 8) * WSTRIDE) + ((lane >> 3) & 1) * 8) * 2;
    uint32_t wibase = (uint32_t)__cvta_generic_to_shared(winh);
    uint32_t laneWi = wibase +
        ((((lane & 7) + ((lane >> 4) & 1) * 8) * WINSTR) + ((lane >> 3) & 1) * 8) * 2;
    uint32_t wobase = (uint32_t)__cvta_generic_to_shared(woh);
    uint32_t laneO = wobase + (((lane & 7) * OWSTR) + ((lane >> 3) & 1) * 8) * 2;

    /* prefetch first tile: this thread owns row tile*384 + warp*32 + lane */
    float3 xpre = make_float3(0.f, 0.f, 0.f);
    int ipre = 0;
    {
        long r = (long)blockIdx.x * TILE_M + warp * 32 + lane;
        if (r < N_EDGES) {
            xpre = make_float3(ef[r * 3], ef[r * 3 + 1], ef[r * 3 + 2]);
            ipre = ids[r];
        }
    }

    for (int tile = blockIdx.x; tile < NTILES; tile += gridDim.x) {
        /* ---- distribute x within the warp via shuffles ---- */
        uint32_t a0[2], a1[2];
        #pragma unroll
        for (int s2 = 0; s2 < 2; s2++) {
            int ra = gid + s2 * 16, rb = ra + 8;
            float ax = __shfl_sync(0xffffffffu, xpre.x, ra);
            float ay = __shfl_sync(0xffffffffu, xpre.y, ra);
            float az = __shfl_sync(0xffffffffu, xpre.z, ra);
            float bx = __shfl_sync(0xffffffffu, xpre.x, rb);
            float by = __shfl_sync(0xffffffffu, xpre.y, rb);
            float bz = __shfl_sync(0xffffffffu, xpre.z, rb);
            a0[s2] = (q == 0) ? pack_h2(ax, ay) : (q == 1) ? pack_h2(az, 1.f) : 0u;
            a1[s2] = (q == 0) ? pack_h2(bx, by) : (q == 1) ? pack_h2(bz, 1.f) : 0u;
        }
        const int icur = ipre;

        /* prefetch next tile while this one computes */
        {
            int nt = tile + gridDim.x;
            xpre = make_float3(0.f, 0.f, 0.f);
            if (nt < NTILES) {
                long r = (long)nt * TILE_M + warp * 32 + lane;
                if (r < N_EDGES) {
                    xpre = make_float3(ef[r * 3], ef[r * 3 + 1], ef[r * 3 + 2]);
                    ipre = ids[r];
                }
            }
        }

        /* ---- residual stream, packed fp16 A-fragment layout ---- */
        uint32_t hp[2][32];
        #pragma unroll
        for (int s2 = 0; s2 < 2; s2++)
            #pragma unroll
            for (int i = 0; i < 32; i++) hp[s2][i] = 0u;

        /* ---- input layer on the tensor pipe ---- */
        #pragma unroll
        for (int jp = 0; jp < 8; jp++) {
            uint32_t b0, b1, b2, b3;
            ldsm_x4(b0, b1, b2, b3, laneWi + (uint32_t)(jp * 16 * WINSTR * 2));
            #pragma unroll
            for (int s2 = 0; s2 < 2; s2++) {
                int j0 = 2 * jp, j1 = 2 * jp + 1;
                int i00 = 4 * (j0 >> 1) + (j0 & 1) * 2;
                int i01 = 4 * (j1 >> 1) + (j1 & 1) * 2;
                mma16816h(&hp[s2][i00], a0[s2], a1[s2], 0u, 0u, b0, b1);
                mma16816h(&hp[s2][i01], a0[s2], a1[s2], 0u, 0u, b2, b3);
            }
        }

        /* sum of squares of h */
        float ssf[2][2];
        #pragma unroll
        for (int s2 = 0; s2 < 2; s2++) {
            uint32_t n0 = 0u, n1 = 0u;
            #pragma unroll
            for (int i = 0; i < 16; i++) {
                n0 = hfma2_u(hp[s2][2 * i],     hp[s2][2 * i],     n0);
                n1 = hfma2_u(hp[s2][2 * i + 1], hp[s2][2 * i + 1], n1);
            }
            float2 v0 = unpack_h2(n0), v1 = unpack_h2(n1);
            ssf[s2][0] = v0.x + v0.y;
            ssf[s2][1] = v1.x + v1.y;
        }

        /* ---- 4 residual blocks: j-pair-outer, relu overlapped ---- */
        #pragma unroll 1
        for (int blk = 0; blk < NRB; blk++) {
            uint32_t sch[2][2];
            #pragma unroll
            for (int s2 = 0; s2 < 2; s2++)
                #pragma unroll
                for (int g = 0; g < 2; g++) {
                    float v = ssf[s2][g];
                    v += __shfl_xor_sync(0xffffffffu, v, 1);
                    v += __shfl_xor_sync(0xffffffffu, v, 2);
                    float s = rsqrtf(v * (1.f / HID) + RMS_EPS);
                    sch[s2][g] = pack_h2(s, s);
                }

            uint32_t y[2][16][2];
            uint32_t lb = laneB + blk * (HID * WSTRIDE * 2);
            const uint32_t* bb2 = brsh + blk * 64;

            #pragma unroll
            for (int jp = 0; jp < 8; jp++) {
                int j0 = 2 * jp, j1 = 2 * jp + 1;
                y[0][j0][0] = y[0][j0][1] = y[0][j1][0] = y[0][j1][1] = 0u;
                y[1][j0][0] = y[1][j0][1] = y[1][j1][0] = y[1][j1][1] = 0u;
                #pragma unroll
                for (int ks = 0; ks < 8; ks++) {
                    uint32_t b0, b1, b2, b3;
                    ldsm_x4(b0, b1, b2, b3,
                            lb + (uint32_t)((jp * 16 * WSTRIDE + ks * 16) * 2));
                    mma16816h(y[0][j0], hp[0][4*ks], hp[0][4*ks+1], hp[0][4*ks+2], hp[0][4*ks+3], b0, b1);
                    mma16816h(y[0][j1], hp[0][4*ks], hp[0][4*ks+1], hp[0][4*ks+2], hp[0][4*ks+3], b2, b3);
                    mma16816h(y[1][j0], hp[1][4*ks], hp[1][4*ks+1], hp[1][4*ks+2], hp[1][4*ks+3], b0, b1);
                    mma16816h(y[1][j1], hp[1][4*ks], hp[1][4*ks+1], hp[1][4*ks+2], hp[1][4*ks+3], b2, b3);
                }
                uint32_t bbA = bb2[j0 * 4 + q], bbB = bb2[j1 * 4 + q];
                #pragma unroll
                for (int s2 = 0; s2 < 2; s2++) {
                    y[s2][j0][0] = hmax2z_u(hfma2_u(y[s2][j0][0], sch[s2][0], bbA));
                    y[s2][j0][1] = hmax2z_u(hfma2_u(y[s2][j0][1], sch[s2][1], bbA));
                    y[s2][j1][0] = hmax2z_u(hfma2_u(y[s2][j1][0], sch[s2][0], bbB));
                    y[s2][j1][1] = hmax2z_u(hfma2_u(y[s2][j1][1], sch[s2][1], bbB));
                }
            }

            /* commit residual; sum-of-squares only needed for blocks 0..NRB-2 */
            if (blk < NRB - 1) {
                #pragma unroll
                for (int s2 = 0; s2 < 2; s2++) {
                    uint32_t n0 = 0u, n1 = 0u;
                    #pragma unroll
                    for (int j = 0; j < 16; j++) {
                        int i0 = 4 * (j >> 1) + (j & 1) * 2;
                        hp[s2][i0]     = hadd2_u(hp[s2][i0],     y[s2][j][0]);
                        hp[s2][i0 + 1] = hadd2_u(hp[s2][i0 + 1], y[s2][j][1]);
                        n0 = hfma2_u(hp[s2][i0],     hp[s2][i0],     n0);
                        n1 = hfma2_u(hp[s2][i0 + 1], hp[s2][i0 + 1], n1);
                    }
                    float2 v0 = unpack_h2(n0), v1 = unpack_h2(n1);
                    ssf[s2][0] = v0.x + v0.y;
                    ssf[s2][1] = v1.x + v1.y;
                }
            } else {
                #pragma unroll
                for (int s2 = 0; s2 < 2; s2++)
                    #pragma unroll
                    for (int j = 0; j < 16; j++) {
                        int i0 = 4 * (j >> 1) + (j & 1) * 2;
                        hp[s2][i0]     = hadd2_u(hp[s2][i0],     y[s2][j][0]);
                        hp[s2][i0 + 1] = hadd2_u(hp[s2][i0 + 1], y[s2][j][1]);
                    }
            }
        }

        /* ---- output layer on the tensor pipe (f32 accum, n=8 tile, col0 live) ---- */
        float d[2][4];
        d[0][0] = d[0][1] = d[0][2] = d[0][3] = 0.f;
        d[1][0] = d[1][1] = d[1][2] = d[1][3] = 0.f;
        #pragma unroll
        for (int ks = 0; ks < 8; ks++) {
            uint32_t b0, b1;
            ldsm_x2(b0, b1, laneO + (uint32_t)(ks * 32));
            mma16816f(d[0], hp[0][4*ks], hp[0][4*ks+1], hp[0][4*ks+2], hp[0][4*ks+3], b0, b1);
            mma16816f(d[1], hp[1][4*ks], hp[1][4*ks+1], hp[1][4*ks+2], hp[1][4*ks+3], b0, b1);
        }
        int idA[2], idB[2];
        #pragma unroll
        for (int s2 = 0; s2 < 2; s2++) {
            idA[s2] = __shfl_sync(0xffffffffu, icur, s2 * 16 + gid);
            idB[s2] = __shfl_sync(0xffffffffu, icur, s2 * 16 + gid + 8);
        }
        if (q == 0) {
            #pragma unroll
            for (int s2 = 0; s2 < 2; s2++) {
                long r0 = (long)tile * TILE_M + warp * 32 + s2 * 16 + gid;
                long r1 = r0 + 8;
                float l0 = d[s2][0] + bout, l1 = d[s2][2] + bout;
                if (r0 < N_EDGES) {
                    g_logits[r0] = l0;
                    atomicMax(&g_segmax[idA[s2]], enc_f(l0));
                }
                if (r1 < N_EDGES) {
                    g_logits[r1] = l1;
                    atomicMax(&g_segmax[idB[s2]], enc_f(l1));
                }
            }
        }
    }

    grid_bar();   /* all logits + segmax complete */

    /* ---- phase 2: exp + warp-aggregated segment sums ---- */
    for (int i = gtid; i < N_EDGES + (gstride - N_EDGES % gstride) % gstride; i += gstride) {
        int s = -1;
        float e = 0.f;
        if (i < N_EDGES) {
            s = ids[i];
            float m = dec_f(g_segmax[s]);
            e = expf(g_logits[i] - m);
            out[i] = e;
        }
        unsigned grp = __match_any_sync(0xffffffffu, s);
        int lo = __ffs(grp) - 1;
        int hi = 31 - __clz(grp);
        float v = e;
        #pragma unroll
        for (int off = 16; off; off >>= 1) {
            float t = __shfl_down_sync(0xffffffffu, v, off);
            if (lane + off <= hi) v += t;
        }
        if (lane == lo && s >= 0) atomicAdd(&g_segsum[s], v);
    }

    grid_bar();   /* all segment sums complete */

    /* ---- phase 3: normalize ---- */
    for (int i = gtid; i < N_EDGES; i += gstride)
        out[i] = out[i] / g_segsum[ids[i]];
}

extern "C" void kernel_launch(void* const* d_in, const int* in_sizes, int n_in,
                              void* d_out, int out_size)
{
    const float* ef    = (const float*)d_in[0];
    const int*   ids   = (const int*)d_in[1];
    const float* W_in  = (const float*)d_in[2];
    const float* b_in  = (const float*)d_in[3];
    const float* rms_w = (const float*)d_in[4];
    const float* W_res = (const float*)d_in[5];
    const float* b_res = (const float*)d_in[6];
    const float* W_out = (const float*)d_in[7];
    const float* b_out = (const float*)d_in[8];
    float* out = (float*)d_out;

    cudaFuncSetAttribute(mlp_kernel, cudaFuncAttributeMaxDynamicSharedMemorySize, SMEM_BYTES);

    int dev = 0, sms = 148;
    cudaGetDevice(&dev);
    cudaDeviceGetAttribute(&sms, cudaDevAttrMultiProcessorCount, dev);
    if (sms <= 0) sms = 148;

    mlp_kernel<<<sms, NTHREADS, SMEM_BYTES>>>(ef, ids, W_in, b_in, rms_w,
                                              W_res, b_res, W_out, b_out, out);
}

// round 15
// speedup vs baseline: 1.0325x; 1.0325x over previous
#include <cuda_runtime.h>
#include <cuda_fp16.h>
#include <cstdint>

#define N_EDGES  2000000
#define NUM_SEGS 500000
#define HID      128
#define NRB      4
#define TILE_M   256
#define NTILES   ((N_EDGES + TILE_M - 1) / TILE_M)   /* 7813, last tile 128 rows */
#define NTHREADS 256
#define WSTRIDE  136                  /* halves per W row: 128 + 8 pad */
#define WINSTR   24                   /* halves per W_in row: 16 + 8 pad */
#define OWSTR    136                  /* halves per w_out ldsm row */
#define RMS_EPS  1.1920928955078125e-07f

/* SMEM layout (bytes) */
#define OFF_W     0
#define SZ_W      (NRB * HID * WSTRIDE * 2)          /* 139264 */
#define OFF_WIN16 (OFF_W + SZ_W)                     /* half[128*24] ldsm layout */
#define OFF_BRESH (OFF_WIN16 + HID * WINSTR * 2)     /* half2[4*64]  */
#define OFF_WOH   (OFF_BRESH + NRB * 64 * 4)         /* half[8*136] w_out ldsm B-layout */
#define SMEM_BYTES (OFF_WOH + 8 * OWSTR * 2)

__device__ float    g_logits[N_EDGES];
__device__ unsigned g_segmax[NUM_SEGS];
__device__ float    g_segsum[NUM_SEGS];

__device__ __forceinline__ unsigned enc_f(float f) {
    unsigned b = __float_as_uint(f);
    return (b & 0x80000000u) ? ~b : (b | 0x80000000u);
}
__device__ __forceinline__ float dec_f(unsigned k) {
    unsigned b = (k & 0x80000000u) ? (k & 0x7FFFFFFFu) : ~k;
    return __uint_as_float(b);
}
__device__ __forceinline__ uint32_t pack_h2(float lo, float hi) {
    __half2 h = __floats2half2_rn(lo, hi);
    return *reinterpret_cast<uint32_t*>(&h);
}
__device__ __forceinline__ float2 unpack_h2(uint32_t u) {
    return __half22float2(*reinterpret_cast<__half2*>(&u));
}
__device__ __forceinline__ uint32_t hadd2_u(uint32_t a, uint32_t b) {
    __half2 r = __hadd2(*reinterpret_cast<__half2*>(&a), *reinterpret_cast<__half2*>(&b));
    return *reinterpret_cast<uint32_t*>(&r);
}
__device__ __forceinline__ uint32_t hmax2z_u(uint32_t a) {
    __half2 z = __float2half2_rn(0.f);
    __half2 r = __hmax2(*reinterpret_cast<__half2*>(&a), z);
    return *reinterpret_cast<uint32_t*>(&r);
}
__device__ __forceinline__ uint32_t hfma2_u(uint32_t a, uint32_t b, uint32_t c) {
    __half2 r = __hfma2(*reinterpret_cast<__half2*>(&a),
                        *reinterpret_cast<__half2*>(&b),
                        *reinterpret_cast<__half2*>(&c));
    return *reinterpret_cast<uint32_t*>(&r);
}
__device__ __forceinline__ void ldsm_x4(uint32_t& r0, uint32_t& r1, uint32_t& r2, uint32_t& r3,
                                        uint32_t addr) {
    asm volatile("ldmatrix.sync.aligned.m8n8.x4.shared.b16 {%0,%1,%2,%3}, [%4];\n"
                 : "=r"(r0), "=r"(r1), "=r"(r2), "=r"(r3) : "r"(addr));
}
__device__ __forceinline__ void ldsm_x2(uint32_t& r0, uint32_t& r1, uint32_t addr) {
    asm volatile("ldmatrix.sync.aligned.m8n8.x2.shared.b16 {%0,%1}, [%2];\n"
                 : "=r"(r0), "=r"(r1) : "r"(addr));
}
__device__ __forceinline__ void mma16816h(uint32_t* d,
        uint32_t a0, uint32_t a1, uint32_t a2, uint32_t a3,
        uint32_t b0, uint32_t b1) {
    asm volatile("mma.sync.aligned.m16n8k16.row.col.f16.f16.f16.f16 "
                 "{%0,%1}, {%2,%3,%4,%5}, {%6,%7}, {%0,%1};\n"
                 : "+r"(d[0]), "+r"(d[1])
                 : "r"(a0), "r"(a1), "r"(a2), "r"(a3), "r"(b0), "r"(b1));
}
__device__ __forceinline__ void mma16816f(float* d,
        uint32_t a0, uint32_t a1, uint32_t a2, uint32_t a3,
        uint32_t b0, uint32_t b1) {
    asm volatile("mma.sync.aligned.m16n8k16.row.col.f32.f16.f16.f32 "
                 "{%0,%1,%2,%3}, {%4,%5,%6,%7}, {%8,%9}, {%0,%1,%2,%3};\n"
                 : "+f"(d[0]), "+f"(d[1]), "+f"(d[2]), "+f"(d[3])
                 : "r"(a0), "r"(a1), "r"(a2), "r"(a3), "r"(b0), "r"(b1));
}

__global__ void __launch_bounds__(NTHREADS, 1)
mlp_kernel(const float* __restrict__ ef, const int* __restrict__ ids,
           const float* __restrict__ W_in, const float* __restrict__ b_in,
           const float* __restrict__ rms_w, const float* __restrict__ W_res,
           const float* __restrict__ b_res, const float* __restrict__ W_out,
           const float* __restrict__ b_out)
{
    extern __shared__ char smem[];
    __half*   Wh   = (__half*)(smem + OFF_W);
    __half*   winh = (__half*)(smem + OFF_WIN16);
    uint32_t* brsh = (uint32_t*)(smem + OFF_BRESH);
    __half*   woh  = (__half*)(smem + OFF_WOH);

    const int tid = threadIdx.x;

    /* ---- stage weights once per CTA; fold rms_w (per-k) into W_res ---- */
    for (int idx = tid; idx < NRB * HID * HID; idx += NTHREADS) {
        int i   = idx >> 14;
        int rem = idx & 16383;
        int n   = rem >> 7;
        int k   = rem & 127;
        float w = W_res[idx] * rms_w[i * HID + k];
        Wh[(i * HID + n) * WSTRIDE + k] = __float2half(w);
    }
    for (int idx = tid; idx < HID * 16; idx += NTHREADS) {
        int n = idx >> 4, k = idx & 15;
        float v = (k < 3) ? W_in[n * 3 + k] : (k == 3 ? b_in[n] : 0.f);
        winh[n * WINSTR + k] = __float2half(v);
    }
    for (int idx = tid; idx < HID * (WINSTR - 16); idx += NTHREADS) {
        int n = idx / (WINSTR - 16), k = 16 + idx % (WINSTR - 16);
        winh[n * WINSTR + k] = __float2half(0.f);
    }
    for (int idx = tid; idx < 8 * OWSTR; idx += NTHREADS) {
        int n = idx / OWSTR, k = idx % OWSTR;
        woh[idx] = __float2half((n == 0 && k < HID) ? W_out[k] : 0.f);
    }
    for (int idx = tid; idx < NRB * 64; idx += NTHREADS) {
        int i = idx >> 6, c2 = idx & 63;
        brsh[idx] = pack_h2(b_res[i * HID + 2 * c2], b_res[i * HID + 2 * c2 + 1]);
    }
    __syncthreads();   /* ONLY block sync — weights read-only afterwards */

    const float bout = b_out[0];
    const int warp = tid >> 5, lane = tid & 31;
    const int q = lane & 3, gid = lane >> 2;

    uint32_t wbase = (uint32_t)__cvta_generic_to_shared(Wh);
    uint32_t laneB = wbase +
        ((((lane & 7) + ((lane >> 4) & 1) * 8) * WSTRIDE) + ((lane >> 3) & 1) * 8) * 2;
    uint32_t wibase = (uint32_t)__cvta_generic_to_shared(winh);
    uint32_t laneWi = wibase +
        ((((lane & 7) + ((lane >> 4) & 1) * 8) * WINSTR) + ((lane >> 3) & 1) * 8) * 2;
    uint32_t wobase = (uint32_t)__cvta_generic_to_shared(woh);
    uint32_t laneO = wobase + (((lane & 7) * OWSTR) + ((lane >> 3) & 1) * 8) * 2;

    /* prefetch first tile: this thread owns row tile*256 + warp*32 + lane */
    float3 xpre = make_float3(0.f, 0.f, 0.f);
    int ipre = 0;
    {
        long r = (long)blockIdx.x * TILE_M + warp * 32 + lane;
        if (r < N_EDGES) {
            xpre = make_float3(ef[r * 3], ef[r * 3 + 1], ef[r * 3 + 2]);
            ipre = ids[r];
        }
    }

    for (int tile = blockIdx.x; tile < NTILES; tile += gridDim.x) {
        /* ---- distribute x within the warp via shuffles ---- */
        uint32_t a0[2], a1[2];
        #pragma unroll
        for (int s2 = 0; s2 < 2; s2++) {
            int ra = gid + s2 * 16, rb = ra + 8;
            float ax = __shfl_sync(0xffffffffu, xpre.x, ra);
            float ay = __shfl_sync(0xffffffffu, xpre.y, ra);
            float az = __shfl_sync(0xffffffffu, xpre.z, ra);
            float bx = __shfl_sync(0xffffffffu, xpre.x, rb);
            float by = __shfl_sync(0xffffffffu, xpre.y, rb);
            float bz = __shfl_sync(0xffffffffu, xpre.z, rb);
            a0[s2] = (q == 0) ? pack_h2(ax, ay) : (q == 1) ? pack_h2(az, 1.f) : 0u;
            a1[s2] = (q == 0) ? pack_h2(bx, by) : (q == 1) ? pack_h2(bz, 1.f) : 0u;
        }
        const int icur = ipre;

        /* prefetch next tile while this one computes */
        {
            int nt = tile + gridDim.x;
            xpre = make_float3(0.f, 0.f, 0.f);
            if (nt < NTILES) {
                long r = (long)nt * TILE_M + warp * 32 + lane;
                if (r < N_EDGES) {
                    xpre = make_float3(ef[r * 3], ef[r * 3 + 1], ef[r * 3 + 2]);
                    ipre = ids[r];
                }
            }
        }

        /* ---- residual stream, packed fp16 A-fragment layout ---- */
        uint32_t hp[2][32];
        #pragma unroll
        for (int s2 = 0; s2 < 2; s2++)
            #pragma unroll
            for (int i = 0; i < 32; i++) hp[s2][i] = 0u;

        /* ---- input layer on the tensor pipe ---- */
        #pragma unroll
        for (int jp = 0; jp < 8; jp++) {
            uint32_t b0, b1, b2, b3;
            ldsm_x4(b0, b1, b2, b3, laneWi + (uint32_t)(jp * 16 * WINSTR * 2));
            #pragma unroll
            for (int s2 = 0; s2 < 2; s2++) {
                int j0 = 2 * jp, j1 = 2 * jp + 1;
                int i00 = 4 * (j0 >> 1) + (j0 & 1) * 2;
                int i01 = 4 * (j1 >> 1) + (j1 & 1) * 2;
                mma16816h(&hp[s2][i00], a0[s2], a1[s2], 0u, 0u, b0, b1);
                mma16816h(&hp[s2][i01], a0[s2], a1[s2], 0u, 0u, b2, b3);
            }
        }

        /* sum of squares of h */
        float ssf[2][2];
        #pragma unroll
        for (int s2 = 0; s2 < 2; s2++) {
            uint32_t n0 = 0u, n1 = 0u;
            #pragma unroll
            for (int i = 0; i < 16; i++) {
                n0 = hfma2_u(hp[s2][2 * i],     hp[s2][2 * i],     n0);
                n1 = hfma2_u(hp[s2][2 * i + 1], hp[s2][2 * i + 1], n1);
            }
            float2 v0 = unpack_h2(n0), v1 = unpack_h2(n1);
            ssf[s2][0] = v0.x + v0.y;
            ssf[s2][1] = v1.x + v1.y;
        }

        /* ---- 4 residual blocks: quad-j groups, 8-way independent MMA chains ---- */
        #pragma unroll 1
        for (int blk = 0; blk < NRB; blk++) {
            uint32_t sch[2][2];
            #pragma unroll
            for (int s2 = 0; s2 < 2; s2++)
                #pragma unroll
                for (int g = 0; g < 2; g++) {
                    float v = ssf[s2][g];
                    v += __shfl_xor_sync(0xffffffffu, v, 1);
                    v += __shfl_xor_sync(0xffffffffu, v, 2);
                    float s = rsqrtf(v * (1.f / HID) + RMS_EPS);
                    sch[s2][g] = pack_h2(s, s);
                }

            uint32_t y[2][16][2];
            uint32_t lb = laneB + blk * (HID * WSTRIDE * 2);
            const uint32_t* bb2 = brsh + blk * 64;

            #pragma unroll
            for (int jq = 0; jq < 4; jq++) {
                int j0 = 4 * jq, j1 = j0 + 1, j2 = j0 + 2, j3 = j0 + 3;
                #pragma unroll
                for (int s2 = 0; s2 < 2; s2++) {
                    y[s2][j0][0] = y[s2][j0][1] = 0u;
                    y[s2][j1][0] = y[s2][j1][1] = 0u;
                    y[s2][j2][0] = y[s2][j2][1] = 0u;
                    y[s2][j3][0] = y[s2][j3][1] = 0u;
                }
                #pragma unroll
                for (int ks = 0; ks < 8; ks++) {
                    uint32_t b0, b1, b2, b3, b4, b5, b6, b7;
                    ldsm_x4(b0, b1, b2, b3,
                            lb + (uint32_t)((j0 * 8 * WSTRIDE + ks * 16) * 2));
                    ldsm_x4(b4, b5, b6, b7,
                            lb + (uint32_t)((j2 * 8 * WSTRIDE + ks * 16) * 2));
                    /* 8 independent accumulator chains between dependent issues */
                    mma16816h(y[0][j0], hp[0][4*ks], hp[0][4*ks+1], hp[0][4*ks+2], hp[0][4*ks+3], b0, b1);
                    mma16816h(y[0][j1], hp[0][4*ks], hp[0][4*ks+1], hp[0][4*ks+2], hp[0][4*ks+3], b2, b3);
                    mma16816h(y[0][j2], hp[0][4*ks], hp[0][4*ks+1], hp[0][4*ks+2], hp[0][4*ks+3], b4, b5);
                    mma16816h(y[0][j3], hp[0][4*ks], hp[0][4*ks+1], hp[0][4*ks+2], hp[0][4*ks+3], b6, b7);
                    mma16816h(y[1][j0], hp[1][4*ks], hp[1][4*ks+1], hp[1][4*ks+2], hp[1][4*ks+3], b0, b1);
                    mma16816h(y[1][j1], hp[1][4*ks], hp[1][4*ks+1], hp[1][4*ks+2], hp[1][4*ks+3], b2, b3);
                    mma16816h(y[1][j2], hp[1][4*ks], hp[1][4*ks+1], hp[1][4*ks+2], hp[1][4*ks+3], b4, b5);
                    mma16816h(y[1][j3], hp[1][4*ks], hp[1][4*ks+1], hp[1][4*ks+2], hp[1][4*ks+3], b6, b7);
                }
                /* relu(sc*y + b) in place for the 4 finished j-tiles */
                #pragma unroll
                for (int jj = 0; jj < 4; jj++) {
                    int j = j0 + jj;
                    uint32_t bb = bb2[j * 4 + q];
                    #pragma unroll
                    for (int s2 = 0; s2 < 2; s2++) {
                        y[s2][j][0] = hmax2z_u(hfma2_u(y[s2][j][0], sch[s2][0], bb));
                        y[s2][j][1] = hmax2z_u(hfma2_u(y[s2][j][1], sch[s2][1], bb));
                    }
                }
            }

            /* commit residual; sum-of-squares only needed for blocks 0..NRB-2 */
            if (blk < NRB - 1) {
                #pragma unroll
                for (int s2 = 0; s2 < 2; s2++) {
                    uint32_t n0 = 0u, n1 = 0u;
                    #pragma unroll
                    for (int j = 0; j < 16; j++) {
                        int i0 = 4 * (j >> 1) + (j & 1) * 2;
                        hp[s2][i0]     = hadd2_u(hp[s2][i0],     y[s2][j][0]);
                        hp[s2][i0 + 1] = hadd2_u(hp[s2][i0 + 1], y[s2][j][1]);
                        n0 = hfma2_u(hp[s2][i0],     hp[s2][i0],     n0);
                        n1 = hfma2_u(hp[s2][i0 + 1], hp[s2][i0 + 1], n1);
                    }
                    float2 v0 = unpack_h2(n0), v1 = unpack_h2(n1);
                    ssf[s2][0] = v0.x + v0.y;
                    ssf[s2][1] = v1.x + v1.y;
                }
            } else {
                #pragma unroll
                for (int s2 = 0; s2 < 2; s2++)
                    #pragma unroll
                    for (int j = 0; j < 16; j++) {
                        int i0 = 4 * (j >> 1) + (j & 1) * 2;
                        hp[s2][i0]     = hadd2_u(hp[s2][i0],     y[s2][j][0]);
                        hp[s2][i0 + 1] = hadd2_u(hp[s2][i0 + 1], y[s2][j][1]);
                    }
            }
        }

        /* ---- output layer on the tensor pipe (f32 accum, n=8 tile, col0 live) ---- */
        float d[2][4];
        d[0][0] = d[0][1] = d[0][2] = d[0][3] = 0.f;
        d[1][0] = d[1][1] = d[1][2] = d[1][3] = 0.f;
        #pragma unroll
        for (int ks = 0; ks < 8; ks++) {
            uint32_t b0, b1;
            ldsm_x2(b0, b1, laneO + (uint32_t)(ks * 32));
            mma16816f(d[0], hp[0][4*ks], hp[0][4*ks+1], hp[0][4*ks+2], hp[0][4*ks+3], b0, b1);
            mma16816f(d[1], hp[1][4*ks], hp[1][4*ks+1], hp[1][4*ks+2], hp[1][4*ks+3], b0, b1);
        }
        int idA[2], idB[2];
        #pragma unroll
        for (int s2 = 0; s2 < 2; s2++) {
            idA[s2] = __shfl_sync(0xffffffffu, icur, s2 * 16 + gid);
            idB[s2] = __shfl_sync(0xffffffffu, icur, s2 * 16 + gid + 8);
        }
        if (q == 0) {
            #pragma unroll
            for (int s2 = 0; s2 < 2; s2++) {
                long r0 = (long)tile * TILE_M + warp * 32 + s2 * 16 + gid;
                long r1 = r0 + 8;
                float l0 = d[s2][0] + bout, l1 = d[s2][2] + bout;
                if (r0 < N_EDGES) {
                    g_logits[r0] = l0;
                    atomicMax(&g_segmax[idA[s2]], enc_f(l0));
                }
                if (r1 < N_EDGES) {
                    g_logits[r1] = l1;
                    atomicMax(&g_segmax[idB[s2]], enc_f(l1));
                }
            }
        }
    }
}

__global__ void init_kernel() {
    int i = blockIdx.x * blockDim.x + threadIdx.x;
    if (i < NUM_SEGS) { g_segmax[i] = 0u; g_segsum[i] = 0.f; }
}

__global__ void exp_kernel(const int* __restrict__ ids, float* __restrict__ out) {
    int i = blockIdx.x * blockDim.x + threadIdx.x;
    int lane = threadIdx.x & 31;
    int s = -1;
    float e = 0.f;
    if (i < N_EDGES) {
        s = ids[i];
        float m = dec_f(g_segmax[s]);
        e = expf(g_logits[i] - m);
        out[i] = e;
    }
    unsigned grp = __match_any_sync(0xffffffffu, s);
    int lo = __ffs(grp) - 1;
    int hi = 31 - __clz(grp);
    float v = e;
    #pragma unroll
    for (int off = 16; off; off >>= 1) {
        float t = __shfl_down_sync(0xffffffffu, v, off);
        if (lane + off <= hi) v += t;
    }
    if (lane == lo && s >= 0) atomicAdd(&g_segsum[s], v);
}

__global__ void norm_kernel(const int* __restrict__ ids, float* __restrict__ out) {
    int i = blockIdx.x * blockDim.x + threadIdx.x;
    if (i < N_EDGES) out[i] = out[i] / g_segsum[ids[i]];
}

extern "C" void kernel_launch(void* const* d_in, const int* in_sizes, int n_in,
                              void* d_out, int out_size)
{
    const float* ef    = (const float*)d_in[0];
    const int*   ids   = (const int*)d_in[1];
    const float* W_in  = (const float*)d_in[2];
    const float* b_in  = (const float*)d_in[3];
    const float* rms_w = (const float*)d_in[4];
    const float* W_res = (const float*)d_in[5];
    const float* b_res = (const float*)d_in[6];
    const float* W_out = (const float*)d_in[7];
    const float* b_out = (const float*)d_in[8];
    float* out = (float*)d_out;

    cudaFuncSetAttribute(mlp_kernel, cudaFuncAttributeMaxDynamicSharedMemorySize, SMEM_BYTES);

    int dev = 0, sms = 148;
    cudaGetDevice(&dev);
    cudaDeviceGetAttribute(&sms, cudaDevAttrMultiProcessorCount, dev);
    if (sms <= 0) sms = 148;

    init_kernel<<<(NUM_SEGS + 255) / 256, 256>>>();
    mlp_kernel<<<sms, NTHREADS, SMEM_BYTES>>>(ef, ids, W_in, b_in, rms_w,
                                              W_res, b_res, W_out, b_out);
    exp_kernel<<<(N_EDGES + 255) / 256, 256>>>(ids, out);
    norm_kernel<<<(N_EDGES + 255) / 256, 256>>>(ids, out);
}

// round 16
// speedup vs baseline: 1.0556x; 1.0223x over previous
#include <cuda_runtime.h>
#include <cuda_fp16.h>
#include <cstdint>

#define N_EDGES  2000000
#define NUM_SEGS 500000
#define HID      128
#define NRB      4
#define TILE_M   384
#define NTILES   ((N_EDGES + TILE_M - 1) / TILE_M)   /* 5209, last tile 128 rows */
#define NTHREADS 384
#define WSTRIDE  136                  /* halves per W row: 128 + 8 pad */
#define WINSTR   24                   /* halves per W_in row: 16 + 8 pad */
#define OWSTR    136                  /* halves per w_out ldsm row */
#define RMS_EPS  1.1920928955078125e-07f

/* SMEM layout (bytes) */
#define OFF_W     0
#define SZ_W      (NRB * HID * WSTRIDE * 2)          /* 139264 */
#define OFF_WIN16 (OFF_W + SZ_W)                     /* half[128*24] ldsm layout */
#define OFF_BRESH (OFF_WIN16 + HID * WINSTR * 2)     /* half2[4*64]  */
#define OFF_WOH   (OFF_BRESH + NRB * 64 * 4)         /* half[8*136] w_out ldsm B-layout */
#define SMEM_BYTES (OFF_WOH + 8 * OWSTR * 2)

__device__ float    g_logits[N_EDGES];
__device__ unsigned g_segmax[NUM_SEGS];
__device__ float    g_segsum[NUM_SEGS];

__device__ __forceinline__ unsigned enc_f(float f) {
    unsigned b = __float_as_uint(f);
    return (b & 0x80000000u) ? ~b : (b | 0x80000000u);
}
__device__ __forceinline__ float dec_f(unsigned k) {
    unsigned b = (k & 0x80000000u) ? (k & 0x7FFFFFFFu) : ~k;
    return __uint_as_float(b);
}
__device__ __forceinline__ uint32_t pack_h2(float lo, float hi) {
    __half2 h = __floats2half2_rn(lo, hi);
    return *reinterpret_cast<uint32_t*>(&h);
}
__device__ __forceinline__ float2 unpack_h2(uint32_t u) {
    return __half22float2(*reinterpret_cast<__half2*>(&u));
}
__device__ __forceinline__ uint32_t hadd2_u(uint32_t a, uint32_t b) {
    __half2 r = __hadd2(*reinterpret_cast<__half2*>(&a), *reinterpret_cast<__half2*>(&b));
    return *reinterpret_cast<uint32_t*>(&r);
}
__device__ __forceinline__ uint32_t hmax2z_u(uint32_t a) {
    __half2 z = __float2half2_rn(0.f);
    __half2 r = __hmax2(*reinterpret_cast<__half2*>(&a), z);
    return *reinterpret_cast<uint32_t*>(&r);
}
__device__ __forceinline__ uint32_t hfma2_u(uint32_t a, uint32_t b, uint32_t c) {
    __half2 r = __hfma2(*reinterpret_cast<__half2*>(&a),
                        *reinterpret_cast<__half2*>(&b),
                        *reinterpret_cast<__half2*>(&c));
    return *reinterpret_cast<uint32_t*>(&r);
}
__device__ __forceinline__ void ldsm_x4(uint32_t& r0, uint32_t& r1, uint32_t& r2, uint32_t& r3,
                                        uint32_t addr) {
    asm volatile("ldmatrix.sync.aligned.m8n8.x4.shared.b16 {%0,%1,%2,%3}, [%4];\n"
                 : "=r"(r0), "=r"(r1), "=r"(r2), "=r"(r3) : "r"(addr));
}
__device__ __forceinline__ void ldsm_x2(uint32_t& r0, uint32_t& r1, uint32_t addr) {
    asm volatile("ldmatrix.sync.aligned.m8n8.x2.shared.b16 {%0,%1}, [%2];\n"
                 : "=r"(r0), "=r"(r1) : "r"(addr));
}
__device__ __forceinline__ void mma16816h(uint32_t* d,
        uint32_t a0, uint32_t a1, uint32_t a2, uint32_t a3,
        uint32_t b0, uint32_t b1) {
    asm volatile("mma.sync.aligned.m16n8k16.row.col.f16.f16.f16.f16 "
                 "{%0,%1}, {%2,%3,%4,%5}, {%6,%7}, {%0,%1};\n"
                 : "+r"(d[0]), "+r"(d[1])
                 : "r"(a0), "r"(a1), "r"(a2), "r"(a3), "r"(b0), "r"(b1));
}
__device__ __forceinline__ void mma16816f(float* d,
        uint32_t a0, uint32_t a1, uint32_t a2, uint32_t a3,
        uint32_t b0, uint32_t b1) {
    asm volatile("mma.sync.aligned.m16n8k16.row.col.f32.f16.f16.f32 "
                 "{%0,%1,%2,%3}, {%4,%5,%6,%7}, {%8,%9}, {%0,%1,%2,%3};\n"
                 : "+f"(d[0]), "+f"(d[1]), "+f"(d[2]), "+f"(d[3])
                 : "r"(a0), "r"(a1), "r"(a2), "r"(a3), "r"(b0), "r"(b1));
}

__global__ void __launch_bounds__(NTHREADS, 1)
mlp_kernel(const float* __restrict__ ef, const int* __restrict__ ids,
           const float* __restrict__ W_in, const float* __restrict__ b_in,
           const float* __restrict__ rms_w, const float* __restrict__ W_res,
           const float* __restrict__ b_res, const float* __restrict__ W_out,
           const float* __restrict__ b_out)
{
    extern __shared__ char smem[];
    __half*   Wh   = (__half*)(smem + OFF_W);
    __half*   winh = (__half*)(smem + OFF_WIN16);
    uint32_t* brsh = (uint32_t*)(smem + OFF_BRESH);
    __half*   woh  = (__half*)(smem + OFF_WOH);

    const int tid = threadIdx.x;

    /* ---- stage weights once per CTA; fold rms_w (per-k) into W_res ---- */
    for (int idx = tid; idx < NRB * HID * HID; idx += NTHREADS) {
        int i   = idx >> 14;
        int rem = idx & 16383;
        int n   = rem >> 7;
        int k   = rem & 127;
        float w = W_res[idx] * rms_w[i * HID + k];
        Wh[(i * HID + n) * WSTRIDE + k] = __float2half(w);
    }
    for (int idx = tid; idx < HID * 16; idx += NTHREADS) {
        int n = idx >> 4, k = idx & 15;
        float v = (k < 3) ? W_in[n * 3 + k] : (k == 3 ? b_in[n] : 0.f);
        winh[n * WINSTR + k] = __float2half(v);
    }
    for (int idx = tid; idx < HID * (WINSTR - 16); idx += NTHREADS) {
        int n = idx / (WINSTR - 16), k = 16 + idx % (WINSTR - 16);
        winh[n * WINSTR + k] = __float2half(0.f);
    }
    for (int idx = tid; idx < 8 * OWSTR; idx += NTHREADS) {
        int n = idx / OWSTR, k = idx % OWSTR;
        woh[idx] = __float2half((n == 0 && k < HID) ? W_out[k] : 0.f);
    }
    for (int idx = tid; idx < NRB * 64; idx += NTHREADS) {
        int i = idx >> 6, c2 = idx & 63;
        brsh[idx] = pack_h2(b_res[i * HID + 2 * c2], b_res[i * HID + 2 * c2 + 1]);
    }
    __syncthreads();   /* ONLY block sync — weights read-only afterwards */

    const float bout = b_out[0];
    const int warp = tid >> 5, lane = tid & 31;
    const int q = lane & 3, gid = lane >> 2;

    uint32_t wbase = (uint32_t)__cvta_generic_to_shared(Wh);
    uint32_t laneB = wbase +
        ((((lane & 7) + ((lane >> 4) & 1) * 8) * WSTRIDE) + ((lane >> 3) & 1) * 8) * 2;
    uint32_t wibase = (uint32_t)__cvta_generic_to_shared(winh);
    uint32_t laneWi = wibase +
        ((((lane & 7) + ((lane >> 4) & 1) * 8) * WINSTR) + ((lane >> 3) & 1) * 8) * 2;
    uint32_t wobase = (uint32_t)__cvta_generic_to_shared(woh);
    uint32_t laneO = wobase + (((lane & 7) * OWSTR) + ((lane >> 3) & 1) * 8) * 2;

    /* prefetch first tile: this thread owns row tile*384 + warp*32 + lane */
    float3 xpre = make_float3(0.f, 0.f, 0.f);
    int ipre = 0;
    {
        long r = (long)blockIdx.x * TILE_M + warp * 32 + lane;
        if (r < N_EDGES) {
            xpre = make_float3(ef[r * 3], ef[r * 3 + 1], ef[r * 3 + 2]);
            ipre = ids[r];
        }
    }

    for (int tile = blockIdx.x; tile < NTILES; tile += gridDim.x) {
        /* ---- distribute x within the warp via shuffles ---- */
        uint32_t a0[2], a1[2];
        #pragma unroll
        for (int s2 = 0; s2 < 2; s2++) {
            int ra = gid + s2 * 16, rb = ra + 8;
            float ax = __shfl_sync(0xffffffffu, xpre.x, ra);
            float ay = __shfl_sync(0xffffffffu, xpre.y, ra);
            float az = __shfl_sync(0xffffffffu, xpre.z, ra);
            float bx = __shfl_sync(0xffffffffu, xpre.x, rb);
            float by = __shfl_sync(0xffffffffu, xpre.y, rb);
            float bz = __shfl_sync(0xffffffffu, xpre.z, rb);
            a0[s2] = (q == 0) ? pack_h2(ax, ay) : (q == 1) ? pack_h2(az, 1.f) : 0u;
            a1[s2] = (q == 0) ? pack_h2(bx, by) : (q == 1) ? pack_h2(bz, 1.f) : 0u;
        }
        const int icur = ipre;

        /* prefetch next tile while this one computes */
        {
            int nt = tile + gridDim.x;
            xpre = make_float3(0.f, 0.f, 0.f);
            if (nt < NTILES) {
                long r = (long)nt * TILE_M + warp * 32 + lane;
                if (r < N_EDGES) {
                    xpre = make_float3(ef[r * 3], ef[r * 3 + 1], ef[r * 3 + 2]);
                    ipre = ids[r];
                }
            }
        }

        /* ---- residual stream, packed fp16 A-fragment layout ---- */
        uint32_t hp[2][32];
        #pragma unroll
        for (int s2 = 0; s2 < 2; s2++)
            #pragma unroll
            for (int i = 0; i < 32; i++) hp[s2][i] = 0u;

        /* ---- input layer on the tensor pipe ---- */
        #pragma unroll
        for (int jp = 0; jp < 8; jp++) {
            uint32_t b0, b1, b2, b3;
            ldsm_x4(b0, b1, b2, b3, laneWi + (uint32_t)(jp * 16 * WINSTR * 2));
            #pragma unroll
            for (int s2 = 0; s2 < 2; s2++) {
                int j0 = 2 * jp, j1 = 2 * jp + 1;
                int i00 = 4 * (j0 >> 1) + (j0 & 1) * 2;
                int i01 = 4 * (j1 >> 1) + (j1 & 1) * 2;
                mma16816h(&hp[s2][i00], a0[s2], a1[s2], 0u, 0u, b0, b1);
                mma16816h(&hp[s2][i01], a0[s2], a1[s2], 0u, 0u, b2, b3);
            }
        }

        /* sum of squares of h */
        float ssf[2][2];
        #pragma unroll
        for (int s2 = 0; s2 < 2; s2++) {
            uint32_t n0 = 0u, n1 = 0u;
            #pragma unroll
            for (int i = 0; i < 16; i++) {
                n0 = hfma2_u(hp[s2][2 * i],     hp[s2][2 * i],     n0);
                n1 = hfma2_u(hp[s2][2 * i + 1], hp[s2][2 * i + 1], n1);
            }
            float2 v0 = unpack_h2(n0), v1 = unpack_h2(n1);
            ssf[s2][0] = v0.x + v0.y;
            ssf[s2][1] = v1.x + v1.y;
        }

        /* ---- 4 residual blocks: quad-j groups with sequential B loads ----
           8-deep independent MMA chains, only 4 live B regs at a time */
        #pragma unroll 1
        for (int blk = 0; blk < NRB; blk++) {
            uint32_t sch[2][2];
            #pragma unroll
            for (int s2 = 0; s2 < 2; s2++)
                #pragma unroll
                for (int g = 0; g < 2; g++) {
                    float v = ssf[s2][g];
                    v += __shfl_xor_sync(0xffffffffu, v, 1);
                    v += __shfl_xor_sync(0xffffffffu, v, 2);
                    float s = rsqrtf(v * (1.f / HID) + RMS_EPS);
                    sch[s2][g] = pack_h2(s, s);
                }

            uint32_t y[2][16][2];
            uint32_t lb = laneB + blk * (HID * WSTRIDE * 2);
            const uint32_t* bb2 = brsh + blk * 64;

            #pragma unroll
            for (int jq = 0; jq < 4; jq++) {
                int j0 = 4 * jq, j1 = j0 + 1, j2 = j0 + 2, j3 = j0 + 3;
                #pragma unroll
                for (int s2 = 0; s2 < 2; s2++) {
                    y[s2][j0][0] = y[s2][j0][1] = 0u;
                    y[s2][j1][0] = y[s2][j1][1] = 0u;
                    y[s2][j2][0] = y[s2][j2][1] = 0u;
                    y[s2][j3][0] = y[s2][j3][1] = 0u;
                }
                #pragma unroll
                for (int ks = 0; ks < 8; ks++) {
                    {
                        uint32_t b0, b1, b2, b3;
                        ldsm_x4(b0, b1, b2, b3,
                                lb + (uint32_t)((j0 * 8 * WSTRIDE + ks * 16) * 2));
                        mma16816h(y[0][j0], hp[0][4*ks], hp[0][4*ks+1], hp[0][4*ks+2], hp[0][4*ks+3], b0, b1);
                        mma16816h(y[0][j1], hp[0][4*ks], hp[0][4*ks+1], hp[0][4*ks+2], hp[0][4*ks+3], b2, b3);
                        mma16816h(y[1][j0], hp[1][4*ks], hp[1][4*ks+1], hp[1][4*ks+2], hp[1][4*ks+3], b0, b1);
                        mma16816h(y[1][j1], hp[1][4*ks], hp[1][4*ks+1], hp[1][4*ks+2], hp[1][4*ks+3], b2, b3);
                    }
                    {
                        uint32_t c0, c1, c2, c3;   /* fresh scope: ptxas reuses b0-b3 */
                        ldsm_x4(c0, c1, c2, c3,
                                lb + (uint32_t)((j2 * 8 * WSTRIDE + ks * 16) * 2));
                        mma16816h(y[0][j2], hp[0][4*ks], hp[0][4*ks+1], hp[0][4*ks+2], hp[0][4*ks+3], c0, c1);
                        mma16816h(y[0][j3], hp[0][4*ks], hp[0][4*ks+1], hp[0][4*ks+2], hp[0][4*ks+3], c2, c3);
                        mma16816h(y[1][j2], hp[1][4*ks], hp[1][4*ks+1], hp[1][4*ks+2], hp[1][4*ks+3], c0, c1);
                        mma16816h(y[1][j3], hp[1][4*ks], hp[1][4*ks+1], hp[1][4*ks+2], hp[1][4*ks+3], c2, c3);
                    }
                }
                /* relu(sc*y + b) in place for the 4 finished j-tiles */
                #pragma unroll
                for (int jj = 0; jj < 4; jj++) {
                    int j = j0 + jj;
                    uint32_t bb = bb2[j * 4 + q];
                    #pragma unroll
                    for (int s2 = 0; s2 < 2; s2++) {
                        y[s2][j][0] = hmax2z_u(hfma2_u(y[s2][j][0], sch[s2][0], bb));
                        y[s2][j][1] = hmax2z_u(hfma2_u(y[s2][j][1], sch[s2][1], bb));
                    }
                }
            }

            /* commit residual; sum-of-squares only needed for blocks 0..NRB-2 */
            if (blk < NRB - 1) {
                #pragma unroll
                for (int s2 = 0; s2 < 2; s2++) {
                    uint32_t n0 = 0u, n1 = 0u;
                    #pragma unroll
                    for (int j = 0; j < 16; j++) {
                        int i0 = 4 * (j >> 1) + (j & 1) * 2;
                        hp[s2][i0]     = hadd2_u(hp[s2][i0],     y[s2][j][0]);
                        hp[s2][i0 + 1] = hadd2_u(hp[s2][i0 + 1], y[s2][j][1]);
                        n0 = hfma2_u(hp[s2][i0],     hp[s2][i0],     n0);
                        n1 = hfma2_u(hp[s2][i0 + 1], hp[s2][i0 + 1], n1);
                    }
                    float2 v0 = unpack_h2(n0), v1 = unpack_h2(n1);
                    ssf[s2][0] = v0.x + v0.y;
                    ssf[s2][1] = v1.x + v1.y;
                }
            } else {
                #pragma unroll
                for (int s2 = 0; s2 < 2; s2++)
                    #pragma unroll
                    for (int j = 0; j < 16; j++) {
                        int i0 = 4 * (j >> 1) + (j & 1) * 2;
                        hp[s2][i0]     = hadd2_u(hp[s2][i0],     y[s2][j][0]);
                        hp[s2][i0 + 1] = hadd2_u(hp[s2][i0 + 1], y[s2][j][1]);
                    }
            }
        }

        /* ---- output layer on the tensor pipe (f32 accum, n=8 tile, col0 live) ---- */
        float d[2][4];
        d[0][0] = d[0][1] = d[0][2] = d[0][3] = 0.f;
        d[1][0] = d[1][1] = d[1][2] = d[1][3] = 0.f;
        #pragma unroll
        for (int ks = 0; ks < 8; ks++) {
            uint32_t b0, b1;
            ldsm_x2(b0, b1, laneO + (uint32_t)(ks * 32));
            mma16816f(d[0], hp[0][4*ks], hp[0][4*ks+1], hp[0][4*ks+2], hp[0][4*ks+3], b0, b1);
            mma16816f(d[1], hp[1][4*ks], hp[1][4*ks+1], hp[1][4*ks+2], hp[1][4*ks+3], b0, b1);
        }
        int idA[2], idB[2];
        #pragma unroll
        for (int s2 = 0; s2 < 2; s2++) {
            idA[s2] = __shfl_sync(0xffffffffu, icur, s2 * 16 + gid);
            idB[s2] = __shfl_sync(0xffffffffu, icur, s2 * 16 + gid + 8);
        }
        if (q == 0) {
            #pragma unroll
            for (int s2 = 0; s2 < 2; s2++) {
                long r0 = (long)tile * TILE_M + warp * 32 + s2 * 16 + gid;
                long r1 = r0 + 8;
                float l0 = d[s2][0] + bout, l1 = d[s2][2] + bout;
                if (r0 < N_EDGES) {
                    g_logits[r0] = l0;
                    atomicMax(&g_segmax[idA[s2]], enc_f(l0));
                }
                if (r1 < N_EDGES) {
                    g_logits[r1] = l1;
                    atomicMax(&g_segmax[idB[s2]], enc_f(l1));
                }
            }
        }
    }
}

__global__ void init_kernel() {
    int i = blockIdx.x * blockDim.x + threadIdx.x;
    if (i < NUM_SEGS) { g_segmax[i] = 0u; g_segsum[i] = 0.f; }
}

__global__ void exp_kernel(const int* __restrict__ ids, float* __restrict__ out) {
    int i = blockIdx.x * blockDim.x + threadIdx.x;
    int lane = threadIdx.x & 31;
    int s = -1;
    float e = 0.f;
    if (i < N_EDGES) {
        s = ids[i];
        float m = dec_f(g_segmax[s]);
        e = expf(g_logits[i] - m);
        out[i] = e;
    }
    unsigned grp = __match_any_sync(0xffffffffu, s);
    int lo = __ffs(grp) - 1;
    int hi = 31 - __clz(grp);
    float v = e;
    #pragma unroll
    for (int off = 16; off; off >>= 1) {
        float t = __shfl_down_sync(0xffffffffu, v, off);
        if (lane + off <= hi) v += t;
    }
    if (lane == lo && s >= 0) atomicAdd(&g_segsum[s], v);
}

__global__ void norm_kernel(const int* __restrict__ ids, float* __restrict__ out) {
    int i = blockIdx.x * blockDim.x + threadIdx.x;
    if (i < N_EDGES) out[i] = out[i] / g_segsum[ids[i]];
}

extern "C" void kernel_launch(void* const* d_in, const int* in_sizes, int n_in,
                              void* d_out, int out_size)
{
    const float* ef    = (const float*)d_in[0];
    const int*   ids   = (const int*)d_in[1];
    const float* W_in  = (const float*)d_in[2];
    const float* b_in  = (const float*)d_in[3];
    const float* rms_w = (const float*)d_in[4];
    const float* W_res = (const float*)d_in[5];
    const float* b_res = (const float*)d_in[6];
    const float* W_out = (const float*)d_in[7];
    const float* b_out = (const float*)d_in[8];
    float* out = (float*)d_out;

    cudaFuncSetAttribute(mlp_kernel, cudaFuncAttributeMaxDynamicSharedMemorySize, SMEM_BYTES);

    int dev = 0, sms = 148;
    cudaGetDevice(&dev);
    cudaDeviceGetAttribute(&sms, cudaDevAttrMultiProcessorCount, dev);
    if (sms <= 0) sms = 148;

    init_kernel<<<(NUM_SEGS + 255) / 256, 256>>>();
    mlp_kernel<<<sms, NTHREADS, SMEM_BYTES>>>(ef, ids, W_in, b_in, rms_w,
                                              W_res, b_res, W_out, b_out);
    exp_kernel<<<(N_EDGES + 255) / 256, 256>>>(ids, out);
    norm_kernel<<<(N_EDGES + 255) / 256, 256>>>(ids, out);
}